// round 12
// baseline (speedup 1.0000x reference)
#include <cuda_runtime.h>
#include <cuda_fp16.h>
#include <math.h>
#include <stdint.h>

#define BB 8
#define N1 8192
#define N2 2048
#define C1 128
#define C2 256
#define KIN1 384
#define O1 256
#define O2 128
#define BN_EPS 1e-5f
#define MIN_DIST 1e-10f
#define P_TOTAL (BB * N1)

// ---------------- scratch (no allocations allowed) ----------------
__device__ __half g_p2Th[BB * N2 * C2];               // points2 transposed [B][N2][C2], fp16
__device__ int   g_knn_idx[BB * N1 * 3];
__device__ float g_knn_w[BB * N1 * 3];
__device__ __half g_w0[O1 * KIN1];
__device__ __half g_w1[O2 * O1];
__device__ __half g_x0[BB * N1 * KIN1];               // conv0 B operand [n][k] fp16
__device__ __half g_x2[BB * N1 * O1];                 // conv1 B operand [n][k] fp16
__device__ float g_y1T[BB * N1 * O1];                 // conv0 out (pre-BN) fp32, [n][o]
__device__ float g_y2[BB * O2 * N1];                  // conv1 out (pre-BN), channel-major [o][n]
__device__ float g_sum0[O1], g_sq0[O1], g_sum1[O2], g_sq1[O2];
__device__ float g_scale0[O1], g_shift0[O1], g_scale1[O2], g_shift1[O2];

// ---------------- helpers ----------------
__device__ __forceinline__ uint32_t smem_u32(const void* p) {
    return (uint32_t)__cvta_generic_to_shared(p);
}
__device__ __forceinline__ void cp16(uint32_t dst, const void* src) {
    asm volatile("cp.async.ca.shared.global [%0], [%1], 16;" :: "r"(dst), "l"(src));
}
__device__ __forceinline__ void cp_commit() {
    asm volatile("cp.async.commit_group;" ::: "memory");
}
template <int N>
__device__ __forceinline__ void cp_wait() {
    asm volatile("cp.async.wait_group %0;" :: "n"(N) : "memory");
}
__device__ __forceinline__ void ldmx4(uint32_t a, uint32_t& r0, uint32_t& r1,
                                      uint32_t& r2, uint32_t& r3) {
    asm volatile("ldmatrix.sync.aligned.m8n8.x4.shared.b16 {%0,%1,%2,%3}, [%4];"
                 : "=r"(r0), "=r"(r1), "=r"(r2), "=r"(r3) : "r"(a));
}
__device__ __forceinline__ void mma16816(float* c, const uint32_t* a,
                                         uint32_t b0, uint32_t b1) {
    asm volatile("mma.sync.aligned.m16n8k16.row.col.f32.f16.f16.f32 "
                 "{%0,%1,%2,%3},{%4,%5,%6,%7},{%8,%9},{%0,%1,%2,%3};"
                 : "+f"(c[0]), "+f"(c[1]), "+f"(c[2]), "+f"(c[3])
                 : "r"(a[0]), "r"(a[1]), "r"(a[2]), "r"(a[3]), "r"(b0), "r"(b1));
}
__device__ __forceinline__ bool knn_lt(float ra, int ia, float rb, int ib) {
    return (ra < rb) || (ra == rb && ia < ib);
}

// ---------------- weights convert + stats zero (one launch; graph replays!) ----------------
__global__ void cvt_w_kernel(const float* __restrict__ w0s,
                             const float* __restrict__ w1s) {
    int i = blockIdx.x * blockDim.x + threadIdx.x;
    if (i < O1 * KIN1) g_w0[i] = __float2half_rn(w0s[i]);
    if (i < O2 * O1)   g_w1[i] = __float2half_rn(w1s[i]);
    if (i < O1) { g_sum0[i] = 0.f; g_sq0[i] = 0.f; }
    if (i < O2) { g_sum1[i] = 0.f; g_sq1[i] = 0.f; }
}

// ---------------- transpose points2 [B,C2,N2] -> fp16 [B,N2,C2] ----------------
__global__ __launch_bounds__(256) void transpose_p2_kernel(const float* __restrict__ p2) {
    __shared__ float tile[64][33];
    int b = blockIdx.z, c0 = blockIdx.y * 64, n0 = blockIdx.x * 32;
    int tx = threadIdx.x & 31, ty = threadIdx.x >> 5;
    #pragma unroll
    for (int i = ty; i < 64; i += 8)
        tile[i][tx] = p2[(size_t)b * C2 * N2 + (size_t)(c0 + i) * N2 + n0 + tx];
    __syncthreads();
    #pragma unroll
    for (int i = 0; i < 4; i++) {
        int n = ty * 4 + i;
        __half h0 = __float2half_rn(tile[tx * 2][n]);
        __half h1 = __float2half_rn(tile[tx * 2 + 1][n]);
        uint32_t pk = (uint32_t)__half_as_ushort(h0) | ((uint32_t)__half_as_ushort(h1) << 16);
        *(uint32_t*)&g_p2Th[((size_t)b * N2 + n0 + n) * C2 + c0 + tx * 2] = pk;
    }
}

// ---------------- transpose+cvt points1 [B,C1,N1] -> x0 [n][0..127] fp16 ----------------
__global__ __launch_bounds__(256) void transpose_p1_kernel(const float* __restrict__ p1) {
    __shared__ float tile[64][33];
    int b = blockIdx.z, c0 = blockIdx.y * 64, n0 = blockIdx.x * 32;
    int tx = threadIdx.x & 31, ty = threadIdx.x >> 5;
    #pragma unroll
    for (int i = ty; i < 64; i += 8)
        tile[i][tx] = p1[(size_t)b * C1 * N1 + (size_t)(c0 + i) * N1 + n0 + tx];
    __syncthreads();
    #pragma unroll
    for (int i = 0; i < 4; i++) {
        int n = ty * 4 + i;
        __half h0 = __float2half_rn(tile[tx * 2][n]);
        __half h1 = __float2half_rn(tile[tx * 2 + 1][n]);
        uint32_t pk = (uint32_t)__half_as_ushort(h0) | ((uint32_t)__half_as_ushort(h1) << 16);
        *(uint32_t*)&g_x0[((size_t)b * N1 + n0 + n) * KIN1 + c0 + tx * 2] = pk;
    }
}

// ---------------- 3-NN: 8 lanes per query (N2 split), shfl merge ----------------
// 256 threads = 32 queries/block; warp = 4 queries x 8 segment-lanes.
// Lane seg scans j = 8*jj + seg (8 consecutive float4 = 128B span, conflict-free).
// Rank by r = 0.5|p|^2 - q.p; merge by (r, idx) lexicographic == sequential strict-<.
__global__ __launch_bounds__(256) void knn_kernel(const float* __restrict__ xyz1,
                                                  const float* __restrict__ xyz2) {
    __shared__ float4 s_p[N2];   // (x, y, z, 0.5*|p|^2)
    int b  = blockIdx.x >> 8;            // 256 blocks per batch
    int n0 = (blockIdx.x & 255) << 5;    // 32 queries per block
    const float* x2 = xyz2 + (size_t)b * N2 * 3;
    for (int j = threadIdx.x; j < N2; j += 256) {
        float px = x2[j * 3], py = x2[j * 3 + 1], pz = x2[j * 3 + 2];
        s_p[j] = make_float4(px, py, pz, 0.5f * (px * px + py * py + pz * pz));
    }
    __syncthreads();

    int t = threadIdx.x;
    int w = t >> 5, lane = t & 31;
    int seg = lane >> 2;                 // 0..7
    int n = n0 + w * 4 + (lane & 3);
    const float* q = xyz1 + ((size_t)b * N1 + n) * 3;
    float qx = q[0], qy = q[1], qz = q[2];

    float r0 = 3.4e38f, r1 = 3.4e38f, r2 = 3.4e38f;
    int   i0 = 0, i1 = 0, i2 = 0;
    #pragma unroll 4
    for (int jj = 0; jj < N2 / 8; jj++) {
        int j = (jj << 3) | seg;
        float4 p = s_p[j];
        float r = fmaf(-qx, p.x, fmaf(-qy, p.y, fmaf(-qz, p.z, p.w)));
        if (r < r2) {
            if (r < r1) {
                r2 = r1; i2 = i1;
                if (r < r0) { r1 = r0; i1 = i0; r0 = r; i0 = j; }
                else        { r1 = r; i1 = j; }
            } else { r2 = r; i2 = j; }
        }
    }

    // merge the 8 segment-lane triples: xor 4, 8, 16
    #pragma unroll
    for (int m = 4; m <= 16; m <<= 1) {
        float s0 = __shfl_xor_sync(0xffffffff, r0, m);
        float s1 = __shfl_xor_sync(0xffffffff, r1, m);
        float s2 = __shfl_xor_sync(0xffffffff, r2, m);
        int   j0 = __shfl_xor_sync(0xffffffff, i0, m);
        int   j1 = __shfl_xor_sync(0xffffffff, i1, m);
        int   j2 = __shfl_xor_sync(0xffffffff, i2, m);
        float c0, c1, c2; int d0, d1, d2;
        if (knn_lt(r0, i0, s0, j0)) {
            c0 = r0; d0 = i0;
            if (knn_lt(r1, i1, s0, j0)) {
                c1 = r1; d1 = i1;
                if (knn_lt(r2, i2, s0, j0)) { c2 = r2; d2 = i2; }
                else                        { c2 = s0; d2 = j0; }
            } else {
                c1 = s0; d1 = j0;
                if (knn_lt(r1, i1, s1, j1)) { c2 = r1; d2 = i1; }
                else                        { c2 = s1; d2 = j1; }
            }
        } else {
            c0 = s0; d0 = j0;
            if (knn_lt(s1, j1, r0, i0)) {
                c1 = s1; d1 = j1;
                if (knn_lt(s2, j2, r0, i0)) { c2 = s2; d2 = j2; }
                else                        { c2 = r0; d2 = i0; }
            } else {
                c1 = r0; d1 = i0;
                if (knn_lt(r1, i1, s1, j1)) { c2 = r1; d2 = i1; }
                else                        { c2 = s1; d2 = j1; }
            }
        }
        r0 = c0; r1 = c1; r2 = c2; i0 = d0; i1 = d1; i2 = d2;
    }

    if (seg == 0) {
        float qn = qx * qx + qy * qy + qz * qz;
        float e0 = fmaxf(sqrtf(fmaxf(qn + 2.f * r0, 0.f)), MIN_DIST);
        float e1 = fmaxf(sqrtf(fmaxf(qn + 2.f * r1, 0.f)), MIN_DIST);
        float e2 = fmaxf(sqrtf(fmaxf(qn + 2.f * r2, 0.f)), MIN_DIST);
        float w0 = 1.f / e0, w1 = 1.f / e1, w2 = 1.f / e2;
        float inv = 1.f / (w0 + w1 + w2);
        size_t on = ((size_t)b * N1 + n) * 3;
        g_knn_idx[on] = i0; g_knn_idx[on + 1] = i1; g_knn_idx[on + 2] = i2;
        g_knn_w[on] = w0 * inv; g_knn_w[on + 1] = w1 * inv; g_knn_w[on + 2] = w2 * inv;
    }
}

// ---------------- interpolation (fp16 gather) -> x0 [n][128..383] fp16 ----------------
__global__ __launch_bounds__(256) void interp_kernel() {
    __shared__ int   s_idx[96];
    __shared__ float s_w[96];
    int b  = blockIdx.x >> 8;
    int n0 = (blockIdx.x & 255) << 5;
    int t  = threadIdx.x;
    if (t < 96) {
        size_t base = ((size_t)b * N1 + n0) * 3 + t;
        s_idx[t] = g_knn_idx[base];
        s_w[t]   = g_knn_w[base];
    }
    __syncthreads();
    int c = t;
    #pragma unroll 8
    for (int p = 0; p < 32; p++) {
        int k = p * 3;
        const __half* r0 = g_p2Th + ((size_t)b * N2 + s_idx[k + 0]) * C2 + c;
        const __half* r1 = g_p2Th + ((size_t)b * N2 + s_idx[k + 1]) * C2 + c;
        const __half* r2 = g_p2Th + ((size_t)b * N2 + s_idx[k + 2]) * C2 + c;
        float v = fmaf(s_w[k], __half2float(*r0),
                  fmaf(s_w[k + 1], __half2float(*r1),
                       s_w[k + 2] * __half2float(*r2)));
        g_x0[((size_t)b * N1 + n0 + p) * KIN1 + C1 + c] = __float2half_rn(v);
    }
}

// ---------------- mma.sync conv, single-pass fp16 ----------------
// CTA 128x128, 8 warps (2x4 -> 64x32 each), K-chunk 64, cp.async double buffer.
// SMEM rows padded to 72 fp16 (144 B) -> conflict-free ldmatrix.
// NOTE: mainloop is proven; do not touch. (256,2) spills accumulators (R7).
#define SM_A0 0
#define SM_A1 18432
#define SM_B0 36864
#define SM_B1 55296
#define SMEM_MMA 73728

template <int LAYER>
__global__ void __launch_bounds__(256, 1) conv_mma_kernel(const float* __restrict__ bias) {
    constexpr int K   = (LAYER == 0) ? KIN1 : O1;
    constexpr int NCH = K / 64;
    extern __shared__ char smem[];
    uint32_t sb = smem_u32(smem);

    int tid  = threadIdx.x;
    int lane = tid & 31, wid = tid >> 5;
    int m_off = (wid >> 2) * 64;     // warp m-origin (o)
    int n_off = (wid & 3) * 32;      // warp n-origin (points)
    int b  = blockIdx.x >> 6;
    int n0 = (blockIdx.x & 63) << 7;
    int o0 = blockIdx.y << 7;

    const __half* Wbase = ((LAYER == 0) ? g_w0 : g_w1) + (size_t)o0 * K;
    const __half* Xbase = ((LAYER == 0) ? g_x0 : g_x2) + ((size_t)b * N1 + n0) * K;

    uint32_t lm_off = (uint32_t)(((lane & 7) + ((lane >> 3) & 1) * 8) * 144 + (lane >> 4) * 16);

    float acc[4][4][4];
    #pragma unroll
    for (int mi = 0; mi < 4; mi++)
        #pragma unroll
        for (int ni = 0; ni < 4; ni++)
            #pragma unroll
            for (int r = 0; r < 4; r++) acc[mi][ni][r] = 0.f;

    int ld_row = tid >> 3;           // 32 rows per i-step
    int ld_seg = tid & 7;

    auto issue_chunk = [&](int c, int buf) {
        int kk = c * 64;
        uint32_t A  = sb + (buf ? SM_A1 : SM_A0);
        uint32_t Bf = sb + (buf ? SM_B1 : SM_B0);
        #pragma unroll
        for (int i = 0; i < 4; i++) {
            int row = ld_row + i * 32;
            uint32_t d = (uint32_t)(row * 144 + ld_seg * 16);
            cp16(A + d,  Wbase + (size_t)row * K + kk + ld_seg * 8);
            cp16(Bf + d, Xbase + (size_t)row * K + kk + ld_seg * 8);
        }
        cp_commit();
    };

    issue_chunk(0, 0);
    for (int c = 0; c < NCH; c++) {
        int buf = c & 1;
        if (c + 1 < NCH) { issue_chunk(c + 1, buf ^ 1); cp_wait<1>(); }
        else             { cp_wait<0>(); }
        __syncthreads();

        uint32_t A  = sb + (buf ? SM_A1 : SM_A0) + (uint32_t)(m_off * 144) + lm_off;
        uint32_t Bf = sb + (buf ? SM_B1 : SM_B0) + (uint32_t)(n_off * 144) + lm_off;
        #pragma unroll
        for (int kst = 0; kst < 4; kst++) {
            uint32_t af[4][4], bf[2][4];
            #pragma unroll
            for (int mi = 0; mi < 4; mi++)
                ldmx4(A + (uint32_t)(mi * 16 * 144 + kst * 32),
                      af[mi][0], af[mi][1], af[mi][2], af[mi][3]);
            #pragma unroll
            for (int nj = 0; nj < 2; nj++)
                ldmx4(Bf + (uint32_t)(nj * 16 * 144 + kst * 32),
                      bf[nj][0], bf[nj][1], bf[nj][2], bf[nj][3]);
            #pragma unroll
            for (int mi = 0; mi < 4; mi++)
                #pragma unroll
                for (int ni = 0; ni < 4; ni++)
                    mma16816(acc[mi][ni], af[mi],
                             bf[ni >> 1][ni & 1], bf[ni >> 1][(ni & 1) + 2]);
        }
        __syncthreads();
    }

    // ---- epilogue: stage D to SMEM [o][n] stride 129, then stats + stores ----
    float* sD = (float*)smem;
    #pragma unroll
    for (int mi = 0; mi < 4; mi++) {
        int r0 = m_off + mi * 16 + (lane >> 2);
        #pragma unroll
        for (int ni = 0; ni < 4; ni++) {
            int cc = n_off + ni * 8 + (lane & 3) * 2;
            sD[r0 * 129 + cc]           = acc[mi][ni][0];
            sD[r0 * 129 + cc + 1]       = acc[mi][ni][1];
            sD[(r0 + 8) * 129 + cc]     = acc[mi][ni][2];
            sD[(r0 + 8) * 129 + cc + 1] = acc[mi][ni][3];
        }
    }
    __syncthreads();

    {
        int o = tid & 127;
        int nlo = (tid >> 7) * 64;
        float bi = bias[o0 + o];
        float s = 0.f, s2 = 0.f;
        #pragma unroll 4
        for (int n = nlo; n < nlo + 64; n++) {
            float v = sD[o * 129 + n] + bi;
            s += v;
            s2 = fmaf(v, v, s2);
        }
        float* gs = (LAYER == 0) ? g_sum0 : g_sum1;
        float* gq = (LAYER == 0) ? g_sq0  : g_sq1;
        atomicAdd(&gs[o0 + o], s);
        atomicAdd(&gq[o0 + o], s2);
    }

    if (LAYER == 0) {
        for (int e = tid; e < 128 * 128; e += 256) {
            int n = e >> 7, o = e & 127;
            g_y1T[((size_t)b * N1 + n0 + n) * O1 + o0 + o] = sD[o * 129 + n] + bias[o0 + o];
        }
    } else {
        for (int e = tid; e < 128 * 128; e += 256) {
            int o = e >> 7, n = e & 127;
            g_y2[((size_t)b * O2 + o) * N1 + n0 + n] = sD[o * 129 + n] + bias[o];
        }
    }
}

// ---------------- BN finalize ----------------
template <int LAYER>
__global__ void bn_finalize_kernel(const float* __restrict__ gamma,
                                   const float* __restrict__ beta) {
    constexpr int O = (LAYER == 0) ? O1 : O2;
    int o = threadIdx.x;
    if (o < O) {
        const float inv = 1.0f / (float)P_TOTAL;
        float su = (LAYER == 0) ? g_sum0[o] : g_sum1[o];
        float sq = (LAYER == 0) ? g_sq0[o]  : g_sq1[o];
        float mu  = su * inv;
        float var = sq * inv - mu * mu;
        float sc  = gamma[o] * rsqrtf(var + BN_EPS);
        if (LAYER == 0) { g_scale0[o] = sc; g_shift0[o] = beta[o] - mu * sc; }
        else            { g_scale1[o] = sc; g_shift1[o] = beta[o] - mu * sc; }
    }
}

// ---------------- midpass: y1T (fp32) -> BN0+ReLU -> x2 fp16 ----------------
__global__ __launch_bounds__(256) void midpass_kernel() {
    size_t i4 = (size_t)blockIdx.x * 256 + threadIdx.x;   // float4 index
    float4 v = ((const float4*)g_y1T)[i4];
    int c0 = (int)((i4 * 4) & (O1 - 1));
    float r[4] = {v.x, v.y, v.z, v.w};
    unsigned short h[4];
    #pragma unroll
    for (int j = 0; j < 4; j++) {
        float x = fmaxf(fmaf(r[j], g_scale0[c0 + j], g_shift0[c0 + j]), 0.f);
        h[j] = __half_as_ushort(__float2half_rn(x));
    }
    ((uint2*)g_x2)[i4] = make_uint2((uint32_t)h[0] | ((uint32_t)h[1] << 16),
                                    (uint32_t)h[2] | ((uint32_t)h[3] << 16));
}

// ---------------- final BN1 + ReLU -> output ----------------
__global__ __launch_bounds__(256) void final_kernel(float* __restrict__ out) {
    int i = blockIdx.x * blockDim.x + threadIdx.x;
    float4 v = ((const float4*)g_y2)[i];
    int c = ((i * 4) / N1) & (O2 - 1);
    float sc = g_scale1[c], sh = g_shift1[c];
    v.x = fmaxf(fmaf(v.x, sc, sh), 0.f);
    v.y = fmaxf(fmaf(v.y, sc, sh), 0.f);
    v.z = fmaxf(fmaf(v.z, sc, sh), 0.f);
    v.w = fmaxf(fmaf(v.w, sc, sh), 0.f);
    ((float4*)out)[i] = v;
}

// ---------------- launch ----------------
extern "C" void kernel_launch(void* const* d_in, const int* in_sizes, int n_in,
                              void* d_out, int out_size) {
    const float* xyz1    = (const float*)d_in[0];
    const float* xyz2    = (const float*)d_in[1];
    const float* points1 = (const float*)d_in[2];
    const float* points2 = (const float*)d_in[3];
    const float* w0  = (const float*)d_in[4];
    const float* b0  = (const float*)d_in[5];
    const float* ga0 = (const float*)d_in[6];
    const float* be0 = (const float*)d_in[7];
    const float* w1  = (const float*)d_in[8];
    const float* b1  = (const float*)d_in[9];
    const float* ga1 = (const float*)d_in[10];
    const float* be1 = (const float*)d_in[11];
    float* out = (float*)d_out;

    cudaFuncSetAttribute(conv_mma_kernel<0>, cudaFuncAttributeMaxDynamicSharedMemorySize, SMEM_MMA);
    cudaFuncSetAttribute(conv_mma_kernel<1>, cudaFuncAttributeMaxDynamicSharedMemorySize, SMEM_MMA);

    cvt_w_kernel<<<(O1 * KIN1 + 255) / 256, 256>>>(w0, w1);
    transpose_p2_kernel<<<dim3(N2 / 32, C2 / 64, BB), 256>>>(points2);
    transpose_p1_kernel<<<dim3(N1 / 32, C1 / 64, BB), 256>>>(points1);
    knn_kernel<<<BB * (N1 / 32), 256>>>(xyz1, xyz2);
    interp_kernel<<<BB * (N1 / 32), 256>>>();
    conv_mma_kernel<0><<<dim3(BB * (N1 / 128), O1 / 128), 256, SMEM_MMA>>>(b0);
    bn_finalize_kernel<0><<<1, 256>>>(ga0, be0);
    midpass_kernel<<<(BB * N1 * O1 / 4) / 256, 256>>>();
    conv_mma_kernel<1><<<dim3(BB * (N1 / 128), O2 / 128), 256, SMEM_MMA>>>(b1);
    bn_finalize_kernel<1><<<1, 128>>>(ga1, be1);
    final_kernel<<<(BB * O2 * N1 / 4) / 256, 256>>>(out);
}

// round 13
// speedup vs baseline: 1.1275x; 1.1275x over previous
#include <cuda_runtime.h>
#include <cuda_fp16.h>
#include <math.h>
#include <stdint.h>

#define BB 8
#define N1 8192
#define N2 2048
#define C1 128
#define C2 256
#define KIN1 384
#define O1 256
#define O2 128
#define BN_EPS 1e-5f
#define MIN_DIST 1e-10f
#define P_TOTAL (BB * N1)

// ---------------- scratch (no allocations allowed) ----------------
__device__ __half g_p2Th[BB * N2 * C2];               // points2 transposed [B][N2][C2], fp16
__device__ int   g_knn_idx[BB * N1 * 3];
__device__ float g_knn_w[BB * N1 * 3];
__device__ __half g_w0[O1 * KIN1];
__device__ __half g_w1[O2 * O1];
__device__ __half g_x0[BB * N1 * KIN1];               // conv0 B operand [n][k] fp16
__device__ __half g_x2[BB * N1 * O1];                 // conv1 B operand [n][k] fp16
__device__ float g_y1T[BB * N1 * O1];                 // conv0 out (pre-BN) fp32, [n][o]
__device__ float g_y2[BB * O2 * N1];                  // conv1 out (pre-BN), channel-major [o][n]
__device__ float g_sum0[O1], g_sq0[O1], g_sum1[O2], g_sq1[O2];
__device__ float g_scale0[O1], g_shift0[O1], g_scale1[O2], g_shift1[O2];

// ---------------- helpers ----------------
__device__ __forceinline__ uint32_t smem_u32(const void* p) {
    return (uint32_t)__cvta_generic_to_shared(p);
}
__device__ __forceinline__ void cp16(uint32_t dst, const void* src) {
    asm volatile("cp.async.ca.shared.global [%0], [%1], 16;" :: "r"(dst), "l"(src));
}
__device__ __forceinline__ void cp_commit() {
    asm volatile("cp.async.commit_group;" ::: "memory");
}
template <int N>
__device__ __forceinline__ void cp_wait() {
    asm volatile("cp.async.wait_group %0;" :: "n"(N) : "memory");
}
__device__ __forceinline__ void ldmx4(uint32_t a, uint32_t& r0, uint32_t& r1,
                                      uint32_t& r2, uint32_t& r3) {
    asm volatile("ldmatrix.sync.aligned.m8n8.x4.shared.b16 {%0,%1,%2,%3}, [%4];"
                 : "=r"(r0), "=r"(r1), "=r"(r2), "=r"(r3) : "r"(a));
}
__device__ __forceinline__ void mma16816(float* c, const uint32_t* a,
                                         uint32_t b0, uint32_t b1) {
    asm volatile("mma.sync.aligned.m16n8k16.row.col.f32.f16.f16.f32 "
                 "{%0,%1,%2,%3},{%4,%5,%6,%7},{%8,%9},{%0,%1,%2,%3};"
                 : "+f"(c[0]), "+f"(c[1]), "+f"(c[2]), "+f"(c[3])
                 : "r"(a[0]), "r"(a[1]), "r"(a[2]), "r"(a[3]), "r"(b0), "r"(b1));
}
__device__ __forceinline__ bool knn_lt(float ra, int ia, float rb, int ib) {
    return (ra < rb) || (ra == rb && ia < ib);
}

// ================= fused prep kernel: grid-partitioned roles =================
// blocks [0, 1024)      : knn (R11-proven 4-lane split, 64 queries/block)
// blocks [1024, 3072)   : transpose_p2 -> fp16 [B,N2,C2]
// blocks [3072, 7168)   : transpose_p1 -> x0[:, 0..127] fp16
// blocks [7168, 7552)   : weight cvt + BN-stats zero
// Compute-bound knn overlaps DRAM-bound transposes across the chip.
#define PREP_KNN    1024
#define PREP_TP2    2048
#define PREP_TP1    4096
#define PREP_CVT    384
#define PREP_TOTAL  (PREP_KNN + PREP_TP2 + PREP_TP1 + PREP_CVT)
#define PREP_SMEM   33792

__global__ __launch_bounds__(256) void prep_kernel(const float* __restrict__ xyz1,
                                                   const float* __restrict__ xyz2,
                                                   const float* __restrict__ p2,
                                                   const float* __restrict__ p1,
                                                   const float* __restrict__ w0s,
                                                   const float* __restrict__ w1s) {
    extern __shared__ char sm_raw[];
    int bid = blockIdx.x;
    int t   = threadIdx.x;

    if (bid < PREP_KNN) {
        // ---- role 0: 3-NN, 4 segment-lanes/query, shfl merge (R11 verbatim) ----
        float4* s_p = (float4*)sm_raw;   // (x, y, z, 0.5*|p|^2)
        int b  = bid >> 7;               // 128 blocks per batch
        int n0 = (bid & 127) << 6;       // 64 queries per block
        const float* x2 = xyz2 + (size_t)b * N2 * 3;
        for (int j = t; j < N2; j += 256) {
            float px = x2[j * 3], py = x2[j * 3 + 1], pz = x2[j * 3 + 2];
            s_p[j] = make_float4(px, py, pz, 0.5f * (px * px + py * py + pz * pz));
        }
        __syncthreads();

        int w = t >> 5, lane = t & 31;
        int seg = lane >> 3;             // 0..3
        int n = n0 + w * 8 + (lane & 7);
        const float* q = xyz1 + ((size_t)b * N1 + n) * 3;
        float qx = q[0], qy = q[1], qz = q[2];

        float r0 = 3.4e38f, r1 = 3.4e38f, r2 = 3.4e38f;
        int   i0 = 0, i1 = 0, i2 = 0;
        #pragma unroll 4
        for (int jj = 0; jj < N2 / 4; jj++) {
            int j = (jj << 2) | seg;
            float4 p = s_p[j];
            float r = fmaf(-qx, p.x, fmaf(-qy, p.y, fmaf(-qz, p.z, p.w)));
            if (r < r2) {
                if (r < r1) {
                    r2 = r1; i2 = i1;
                    if (r < r0) { r1 = r0; i1 = i0; r0 = r; i0 = j; }
                    else        { r1 = r; i1 = j; }
                } else { r2 = r; i2 = j; }
            }
        }

        #pragma unroll
        for (int m = 8; m <= 16; m <<= 1) {
            float s0 = __shfl_xor_sync(0xffffffff, r0, m);
            float s1 = __shfl_xor_sync(0xffffffff, r1, m);
            float s2 = __shfl_xor_sync(0xffffffff, r2, m);
            int   j0 = __shfl_xor_sync(0xffffffff, i0, m);
            int   j1 = __shfl_xor_sync(0xffffffff, i1, m);
            int   j2 = __shfl_xor_sync(0xffffffff, i2, m);
            float c0, c1, c2; int d0, d1, d2;
            if (knn_lt(r0, i0, s0, j0)) {
                c0 = r0; d0 = i0;
                if (knn_lt(r1, i1, s0, j0)) {
                    c1 = r1; d1 = i1;
                    if (knn_lt(r2, i2, s0, j0)) { c2 = r2; d2 = i2; }
                    else                        { c2 = s0; d2 = j0; }
                } else {
                    c1 = s0; d1 = j0;
                    if (knn_lt(r1, i1, s1, j1)) { c2 = r1; d2 = i1; }
                    else                        { c2 = s1; d2 = j1; }
                }
            } else {
                c0 = s0; d0 = j0;
                if (knn_lt(s1, j1, r0, i0)) {
                    c1 = s1; d1 = j1;
                    if (knn_lt(s2, j2, r0, i0)) { c2 = s2; d2 = j2; }
                    else                        { c2 = r0; d2 = i0; }
                } else {
                    c1 = r0; d1 = i0;
                    if (knn_lt(r1, i1, s1, j1)) { c2 = r1; d2 = i1; }
                    else                        { c2 = s1; d2 = j1; }
                }
            }
            r0 = c0; r1 = c1; r2 = c2; i0 = d0; i1 = d1; i2 = d2;
        }

        if (seg == 0) {
            float qn = qx * qx + qy * qy + qz * qz;
            float e0 = fmaxf(sqrtf(fmaxf(qn + 2.f * r0, 0.f)), MIN_DIST);
            float e1 = fmaxf(sqrtf(fmaxf(qn + 2.f * r1, 0.f)), MIN_DIST);
            float e2 = fmaxf(sqrtf(fmaxf(qn + 2.f * r2, 0.f)), MIN_DIST);
            float w0 = 1.f / e0, w1 = 1.f / e1, w2 = 1.f / e2;
            float inv = 1.f / (w0 + w1 + w2);
            size_t on = ((size_t)b * N1 + n) * 3;
            g_knn_idx[on] = i0; g_knn_idx[on + 1] = i1; g_knn_idx[on + 2] = i2;
            g_knn_w[on] = w0 * inv; g_knn_w[on + 1] = w1 * inv; g_knn_w[on + 2] = w2 * inv;
        }
    } else if (bid < PREP_KNN + PREP_TP2) {
        // ---- role 1: transpose points2 [B,C2,N2] -> fp16 [B,N2,C2] ----
        float (*tile)[33] = (float (*)[33])sm_raw;
        int idx = bid - PREP_KNN;                    // dim (n:64, c:4, b:8)
        int b  = idx >> 8;
        int rem = idx & 255;
        int c0 = (rem >> 6) << 6;
        int n0 = (rem & 63) << 5;
        int tx = t & 31, ty = t >> 5;
        #pragma unroll
        for (int i = ty; i < 64; i += 8)
            tile[i][tx] = p2[(size_t)b * C2 * N2 + (size_t)(c0 + i) * N2 + n0 + tx];
        __syncthreads();
        #pragma unroll
        for (int i = 0; i < 4; i++) {
            int n = ty * 4 + i;
            __half h0 = __float2half_rn(tile[tx * 2][n]);
            __half h1 = __float2half_rn(tile[tx * 2 + 1][n]);
            uint32_t pk = (uint32_t)__half_as_ushort(h0) | ((uint32_t)__half_as_ushort(h1) << 16);
            *(uint32_t*)&g_p2Th[((size_t)b * N2 + n0 + n) * C2 + c0 + tx * 2] = pk;
        }
    } else if (bid < PREP_KNN + PREP_TP2 + PREP_TP1) {
        // ---- role 2: transpose+cvt points1 [B,C1,N1] -> x0 [n][0..127] fp16 ----
        float (*tile)[33] = (float (*)[33])sm_raw;
        int idx = bid - PREP_KNN - PREP_TP2;         // dim (n:256, c:2, b:8)
        int b  = idx >> 9;
        int rem = idx & 511;
        int c0 = (rem >> 8) << 6;
        int n0 = (rem & 255) << 5;
        int tx = t & 31, ty = t >> 5;
        #pragma unroll
        for (int i = ty; i < 64; i += 8)
            tile[i][tx] = p1[(size_t)b * C1 * N1 + (size_t)(c0 + i) * N1 + n0 + tx];
        __syncthreads();
        #pragma unroll
        for (int i = 0; i < 4; i++) {
            int n = ty * 4 + i;
            __half h0 = __float2half_rn(tile[tx * 2][n]);
            __half h1 = __float2half_rn(tile[tx * 2 + 1][n]);
            uint32_t pk = (uint32_t)__half_as_ushort(h0) | ((uint32_t)__half_as_ushort(h1) << 16);
            *(uint32_t*)&g_x0[((size_t)b * N1 + n0 + n) * KIN1 + c0 + tx * 2] = pk;
        }
    } else {
        // ---- role 3: weight cvt fp32->fp16 + BN-stats zero (graph replays!) ----
        int i = (bid - PREP_KNN - PREP_TP2 - PREP_TP1) * 256 + t;
        if (i < O1 * KIN1) g_w0[i] = __float2half_rn(w0s[i]);
        if (i < O2 * O1)   g_w1[i] = __float2half_rn(w1s[i]);
        if (i < O1) { g_sum0[i] = 0.f; g_sq0[i] = 0.f; }
        if (i < O2) { g_sum1[i] = 0.f; g_sq1[i] = 0.f; }
    }
}

// ---------------- interpolation (fp16 gather) -> x0 [n][128..383] fp16 ----------------
__global__ __launch_bounds__(256) void interp_kernel() {
    __shared__ int   s_idx[96];
    __shared__ float s_w[96];
    int b  = blockIdx.x >> 8;
    int n0 = (blockIdx.x & 255) << 5;
    int t  = threadIdx.x;
    if (t < 96) {
        size_t base = ((size_t)b * N1 + n0) * 3 + t;
        s_idx[t] = g_knn_idx[base];
        s_w[t]   = g_knn_w[base];
    }
    __syncthreads();
    int c = t;
    #pragma unroll 8
    for (int p = 0; p < 32; p++) {
        int k = p * 3;
        const __half* r0 = g_p2Th + ((size_t)b * N2 + s_idx[k + 0]) * C2 + c;
        const __half* r1 = g_p2Th + ((size_t)b * N2 + s_idx[k + 1]) * C2 + c;
        const __half* r2 = g_p2Th + ((size_t)b * N2 + s_idx[k + 2]) * C2 + c;
        float v = fmaf(s_w[k], __half2float(*r0),
                  fmaf(s_w[k + 1], __half2float(*r1),
                       s_w[k + 2] * __half2float(*r2)));
        g_x0[((size_t)b * N1 + n0 + p) * KIN1 + C1 + c] = __float2half_rn(v);
    }
}

// ---------------- mma.sync conv, single-pass fp16 ----------------
// CTA 128x128, 8 warps (2x4 -> 64x32 each), K-chunk 64, cp.async double buffer.
// SMEM rows padded to 72 fp16 (144 B) -> conflict-free ldmatrix.
// NOTE: mainloop is proven; do not touch. (256,2) spills accumulators (R7).
#define SM_A0 0
#define SM_A1 18432
#define SM_B0 36864
#define SM_B1 55296
#define SMEM_MMA 73728

template <int LAYER>
__global__ void __launch_bounds__(256, 1) conv_mma_kernel(const float* __restrict__ bias) {
    constexpr int K   = (LAYER == 0) ? KIN1 : O1;
    constexpr int NCH = K / 64;
    extern __shared__ char smem[];
    uint32_t sb = smem_u32(smem);

    int tid  = threadIdx.x;
    int lane = tid & 31, wid = tid >> 5;
    int m_off = (wid >> 2) * 64;     // warp m-origin (o)
    int n_off = (wid & 3) * 32;      // warp n-origin (points)
    int b  = blockIdx.x >> 6;
    int n0 = (blockIdx.x & 63) << 7;
    int o0 = blockIdx.y << 7;

    const __half* Wbase = ((LAYER == 0) ? g_w0 : g_w1) + (size_t)o0 * K;
    const __half* Xbase = ((LAYER == 0) ? g_x0 : g_x2) + ((size_t)b * N1 + n0) * K;

    uint32_t lm_off = (uint32_t)(((lane & 7) + ((lane >> 3) & 1) * 8) * 144 + (lane >> 4) * 16);

    float acc[4][4][4];
    #pragma unroll
    for (int mi = 0; mi < 4; mi++)
        #pragma unroll
        for (int ni = 0; ni < 4; ni++)
            #pragma unroll
            for (int r = 0; r < 4; r++) acc[mi][ni][r] = 0.f;

    int ld_row = tid >> 3;           // 32 rows per i-step
    int ld_seg = tid & 7;

    auto issue_chunk = [&](int c, int buf) {
        int kk = c * 64;
        uint32_t A  = sb + (buf ? SM_A1 : SM_A0);
        uint32_t Bf = sb + (buf ? SM_B1 : SM_B0);
        #pragma unroll
        for (int i = 0; i < 4; i++) {
            int row = ld_row + i * 32;
            uint32_t d = (uint32_t)(row * 144 + ld_seg * 16);
            cp16(A + d,  Wbase + (size_t)row * K + kk + ld_seg * 8);
            cp16(Bf + d, Xbase + (size_t)row * K + kk + ld_seg * 8);
        }
        cp_commit();
    };

    issue_chunk(0, 0);
    for (int c = 0; c < NCH; c++) {
        int buf = c & 1;
        if (c + 1 < NCH) { issue_chunk(c + 1, buf ^ 1); cp_wait<1>(); }
        else             { cp_wait<0>(); }
        __syncthreads();

        uint32_t A  = sb + (buf ? SM_A1 : SM_A0) + (uint32_t)(m_off * 144) + lm_off;
        uint32_t Bf = sb + (buf ? SM_B1 : SM_B0) + (uint32_t)(n_off * 144) + lm_off;
        #pragma unroll
        for (int kst = 0; kst < 4; kst++) {
            uint32_t af[4][4], bf[2][4];
            #pragma unroll
            for (int mi = 0; mi < 4; mi++)
                ldmx4(A + (uint32_t)(mi * 16 * 144 + kst * 32),
                      af[mi][0], af[mi][1], af[mi][2], af[mi][3]);
            #pragma unroll
            for (int nj = 0; nj < 2; nj++)
                ldmx4(Bf + (uint32_t)(nj * 16 * 144 + kst * 32),
                      bf[nj][0], bf[nj][1], bf[nj][2], bf[nj][3]);
            #pragma unroll
            for (int mi = 0; mi < 4; mi++)
                #pragma unroll
                for (int ni = 0; ni < 4; ni++)
                    mma16816(acc[mi][ni], af[mi],
                             bf[ni >> 1][ni & 1], bf[ni >> 1][(ni & 1) + 2]);
        }
        __syncthreads();
    }

    // ---- epilogue: stage D to SMEM [o][n] stride 129, then stats + stores ----
    float* sD = (float*)smem;
    #pragma unroll
    for (int mi = 0; mi < 4; mi++) {
        int r0 = m_off + mi * 16 + (lane >> 2);
        #pragma unroll
        for (int ni = 0; ni < 4; ni++) {
            int cc = n_off + ni * 8 + (lane & 3) * 2;
            sD[r0 * 129 + cc]           = acc[mi][ni][0];
            sD[r0 * 129 + cc + 1]       = acc[mi][ni][1];
            sD[(r0 + 8) * 129 + cc]     = acc[mi][ni][2];
            sD[(r0 + 8) * 129 + cc + 1] = acc[mi][ni][3];
        }
    }
    __syncthreads();

    {
        int o = tid & 127;
        int nlo = (tid >> 7) * 64;
        float bi = bias[o0 + o];
        float s = 0.f, s2 = 0.f;
        #pragma unroll 4
        for (int n = nlo; n < nlo + 64; n++) {
            float v = sD[o * 129 + n] + bi;
            s += v;
            s2 = fmaf(v, v, s2);
        }
        float* gs = (LAYER == 0) ? g_sum0 : g_sum1;
        float* gq = (LAYER == 0) ? g_sq0  : g_sq1;
        atomicAdd(&gs[o0 + o], s);
        atomicAdd(&gq[o0 + o], s2);
    }

    if (LAYER == 0) {
        for (int e = tid; e < 128 * 128; e += 256) {
            int n = e >> 7, o = e & 127;
            g_y1T[((size_t)b * N1 + n0 + n) * O1 + o0 + o] = sD[o * 129 + n] + bias[o0 + o];
        }
    } else {
        for (int e = tid; e < 128 * 128; e += 256) {
            int o = e >> 7, n = e & 127;
            g_y2[((size_t)b * O2 + o) * N1 + n0 + n] = sD[o * 129 + n] + bias[o];
        }
    }
}

// ---------------- BN finalize ----------------
template <int LAYER>
__global__ void bn_finalize_kernel(const float* __restrict__ gamma,
                                   const float* __restrict__ beta) {
    constexpr int O = (LAYER == 0) ? O1 : O2;
    int o = threadIdx.x;
    if (o < O) {
        const float inv = 1.0f / (float)P_TOTAL;
        float su = (LAYER == 0) ? g_sum0[o] : g_sum1[o];
        float sq = (LAYER == 0) ? g_sq0[o]  : g_sq1[o];
        float mu  = su * inv;
        float var = sq * inv - mu * mu;
        float sc  = gamma[o] * rsqrtf(var + BN_EPS);
        if (LAYER == 0) { g_scale0[o] = sc; g_shift0[o] = beta[o] - mu * sc; }
        else            { g_scale1[o] = sc; g_shift1[o] = beta[o] - mu * sc; }
    }
}

// ---------------- midpass: y1T (fp32) -> BN0+ReLU -> x2 fp16 ----------------
__global__ __launch_bounds__(256) void midpass_kernel() {
    size_t i4 = (size_t)blockIdx.x * 256 + threadIdx.x;   // float4 index
    float4 v = ((const float4*)g_y1T)[i4];
    int c0 = (int)((i4 * 4) & (O1 - 1));
    float r[4] = {v.x, v.y, v.z, v.w};
    unsigned short h[4];
    #pragma unroll
    for (int j = 0; j < 4; j++) {
        float x = fmaxf(fmaf(r[j], g_scale0[c0 + j], g_shift0[c0 + j]), 0.f);
        h[j] = __half_as_ushort(__float2half_rn(x));
    }
    ((uint2*)g_x2)[i4] = make_uint2((uint32_t)h[0] | ((uint32_t)h[1] << 16),
                                    (uint32_t)h[2] | ((uint32_t)h[3] << 16));
}

// ---------------- final BN1 + ReLU -> output ----------------
__global__ __launch_bounds__(256) void final_kernel(float* __restrict__ out) {
    int i = blockIdx.x * blockDim.x + threadIdx.x;
    float4 v = ((const float4*)g_y2)[i];
    int c = ((i * 4) / N1) & (O2 - 1);
    float sc = g_scale1[c], sh = g_shift1[c];
    v.x = fmaxf(fmaf(v.x, sc, sh), 0.f);
    v.y = fmaxf(fmaf(v.y, sc, sh), 0.f);
    v.z = fmaxf(fmaf(v.z, sc, sh), 0.f);
    v.w = fmaxf(fmaf(v.w, sc, sh), 0.f);
    ((float4*)out)[i] = v;
}

// ---------------- launch ----------------
extern "C" void kernel_launch(void* const* d_in, const int* in_sizes, int n_in,
                              void* d_out, int out_size) {
    const float* xyz1    = (const float*)d_in[0];
    const float* xyz2    = (const float*)d_in[1];
    const float* points1 = (const float*)d_in[2];
    const float* points2 = (const float*)d_in[3];
    const float* w0  = (const float*)d_in[4];
    const float* b0  = (const float*)d_in[5];
    const float* ga0 = (const float*)d_in[6];
    const float* be0 = (const float*)d_in[7];
    const float* w1  = (const float*)d_in[8];
    const float* b1  = (const float*)d_in[9];
    const float* ga1 = (const float*)d_in[10];
    const float* be1 = (const float*)d_in[11];
    float* out = (float*)d_out;

    cudaFuncSetAttribute(conv_mma_kernel<0>, cudaFuncAttributeMaxDynamicSharedMemorySize, SMEM_MMA);
    cudaFuncSetAttribute(conv_mma_kernel<1>, cudaFuncAttributeMaxDynamicSharedMemorySize, SMEM_MMA);

    prep_kernel<<<PREP_TOTAL, 256, PREP_SMEM>>>(xyz1, xyz2, points2, points1, w0, w1);
    interp_kernel<<<BB * (N1 / 32), 256>>>();
    conv_mma_kernel<0><<<dim3(BB * (N1 / 128), O1 / 128), 256, SMEM_MMA>>>(b0);
    bn_finalize_kernel<0><<<1, 256>>>(ga0, be0);
    midpass_kernel<<<(BB * N1 * O1 / 4) / 256, 256>>>();
    conv_mma_kernel<1><<<dim3(BB * (N1 / 128), O2 / 128), 256, SMEM_MMA>>>(b1);
    bn_finalize_kernel<1><<<1, 128>>>(ga1, be1);
    final_kernel<<<(BB * O2 * N1 / 4) / 256, 256>>>(out);
}

// round 14
// speedup vs baseline: 1.1484x; 1.0185x over previous
#include <cuda_runtime.h>
#include <cuda_fp16.h>
#include <math.h>
#include <stdint.h>

#define BB 8
#define N1 8192
#define N2 2048
#define C1 128
#define C2 256
#define KIN1 384
#define O1 256
#define O2 128
#define BN_EPS 1e-5f
#define MIN_DIST 1e-10f
#define P_TOTAL (BB * N1)

// ---------------- scratch (no allocations allowed) ----------------
__device__ __half g_p2Th[BB * N2 * C2];               // points2 transposed [B][N2][C2], fp16
__device__ int   g_knn_idx[BB * N1 * 3];
__device__ float g_knn_w[BB * N1 * 3];
__device__ __half g_w0[O1 * KIN1];
__device__ __half g_w1[O2 * O1];
__device__ __half g_x0[BB * N1 * KIN1];               // conv0 B operand [n][k] fp16
__device__ __half g_x2[BB * N1 * O1];                 // conv1 B operand [n][k] fp16
__device__ float g_y1T[BB * N1 * O1];                 // conv0 out (pre-BN) fp32, [n][o]
__device__ float g_y2[BB * O2 * N1];                  // conv1 out (pre-BN), channel-major [o][n]
__device__ float g_sum0[O1], g_sq0[O1], g_sum1[O2], g_sq1[O2];

// ---------------- helpers ----------------
__device__ __forceinline__ uint32_t smem_u32(const void* p) {
    return (uint32_t)__cvta_generic_to_shared(p);
}
__device__ __forceinline__ void cp16(uint32_t dst, const void* src) {
    asm volatile("cp.async.ca.shared.global [%0], [%1], 16;" :: "r"(dst), "l"(src));
}
__device__ __forceinline__ void cp_commit() {
    asm volatile("cp.async.commit_group;" ::: "memory");
}
template <int N>
__device__ __forceinline__ void cp_wait() {
    asm volatile("cp.async.wait_group %0;" :: "n"(N) : "memory");
}
__device__ __forceinline__ void ldmx4(uint32_t a, uint32_t& r0, uint32_t& r1,
                                      uint32_t& r2, uint32_t& r3) {
    asm volatile("ldmatrix.sync.aligned.m8n8.x4.shared.b16 {%0,%1,%2,%3}, [%4];"
                 : "=r"(r0), "=r"(r1), "=r"(r2), "=r"(r3) : "r"(a));
}
__device__ __forceinline__ void mma16816(float* c, const uint32_t* a,
                                         uint32_t b0, uint32_t b1) {
    asm volatile("mma.sync.aligned.m16n8k16.row.col.f32.f16.f16.f32 "
                 "{%0,%1,%2,%3},{%4,%5,%6,%7},{%8,%9},{%0,%1,%2,%3};"
                 : "+f"(c[0]), "+f"(c[1]), "+f"(c[2]), "+f"(c[3])
                 : "r"(a[0]), "r"(a[1]), "r"(a[2]), "r"(a[3]), "r"(b0), "r"(b1));
}
__device__ __forceinline__ bool knn_lt(float ra, int ia, float rb, int ib) {
    return (ra < rb) || (ra == rb && ia < ib);
}

// ================= fused prep kernel: grid-partitioned roles =================
// blocks [0, 1024)      : knn (R11-proven 4-lane split, 64 queries/block)
// blocks [1024, 3072)   : transpose_p2 -> fp16 [B,N2,C2]
// blocks [3072, 7168)   : transpose_p1 -> x0[:, 0..127] fp16
// blocks [7168, 7552)   : weight cvt + BN-stats zero
// Compute-bound knn overlaps DRAM-bound transposes across the chip.
#define PREP_KNN    1024
#define PREP_TP2    2048
#define PREP_TP1    4096
#define PREP_CVT    384
#define PREP_TOTAL  (PREP_KNN + PREP_TP2 + PREP_TP1 + PREP_CVT)
#define PREP_SMEM   33792

__global__ __launch_bounds__(256) void prep_kernel(const float* __restrict__ xyz1,
                                                   const float* __restrict__ xyz2,
                                                   const float* __restrict__ p2,
                                                   const float* __restrict__ p1,
                                                   const float* __restrict__ w0s,
                                                   const float* __restrict__ w1s) {
    extern __shared__ char sm_raw[];
    int bid = blockIdx.x;
    int t   = threadIdx.x;

    if (bid < PREP_KNN) {
        // ---- role 0: 3-NN, 4 segment-lanes/query, shfl merge ----
        float4* s_p = (float4*)sm_raw;   // (x, y, z, 0.5*|p|^2)
        int b  = bid >> 7;               // 128 blocks per batch
        int n0 = (bid & 127) << 6;       // 64 queries per block
        const float* x2 = xyz2 + (size_t)b * N2 * 3;
        for (int j = t; j < N2; j += 256) {
            float px = x2[j * 3], py = x2[j * 3 + 1], pz = x2[j * 3 + 2];
            s_p[j] = make_float4(px, py, pz, 0.5f * (px * px + py * py + pz * pz));
        }
        __syncthreads();

        int w = t >> 5, lane = t & 31;
        int seg = lane >> 3;             // 0..3
        int n = n0 + w * 8 + (lane & 7);
        const float* q = xyz1 + ((size_t)b * N1 + n) * 3;
        float qx = q[0], qy = q[1], qz = q[2];

        float r0 = 3.4e38f, r1 = 3.4e38f, r2 = 3.4e38f;
        int   i0 = 0, i1 = 0, i2 = 0;
        #pragma unroll 4
        for (int jj = 0; jj < N2 / 4; jj++) {
            int j = (jj << 2) | seg;
            float4 p = s_p[j];
            float r = fmaf(-qx, p.x, fmaf(-qy, p.y, fmaf(-qz, p.z, p.w)));
            if (r < r2) {
                if (r < r1) {
                    r2 = r1; i2 = i1;
                    if (r < r0) { r1 = r0; i1 = i0; r0 = r; i0 = j; }
                    else        { r1 = r; i1 = j; }
                } else { r2 = r; i2 = j; }
            }
        }

        #pragma unroll
        for (int m = 8; m <= 16; m <<= 1) {
            float s0 = __shfl_xor_sync(0xffffffff, r0, m);
            float s1 = __shfl_xor_sync(0xffffffff, r1, m);
            float s2 = __shfl_xor_sync(0xffffffff, r2, m);
            int   j0 = __shfl_xor_sync(0xffffffff, i0, m);
            int   j1 = __shfl_xor_sync(0xffffffff, i1, m);
            int   j2 = __shfl_xor_sync(0xffffffff, i2, m);
            float c0, c1, c2; int d0, d1, d2;
            if (knn_lt(r0, i0, s0, j0)) {
                c0 = r0; d0 = i0;
                if (knn_lt(r1, i1, s0, j0)) {
                    c1 = r1; d1 = i1;
                    if (knn_lt(r2, i2, s0, j0)) { c2 = r2; d2 = i2; }
                    else                        { c2 = s0; d2 = j0; }
                } else {
                    c1 = s0; d1 = j0;
                    if (knn_lt(r1, i1, s1, j1)) { c2 = r1; d2 = i1; }
                    else                        { c2 = s1; d2 = j1; }
                }
            } else {
                c0 = s0; d0 = j0;
                if (knn_lt(s1, j1, r0, i0)) {
                    c1 = s1; d1 = j1;
                    if (knn_lt(s2, j2, r0, i0)) { c2 = s2; d2 = j2; }
                    else                        { c2 = r0; d2 = i0; }
                } else {
                    c1 = r0; d1 = i0;
                    if (knn_lt(r1, i1, s1, j1)) { c2 = r1; d2 = i1; }
                    else                        { c2 = s1; d2 = j1; }
                }
            }
            r0 = c0; r1 = c1; r2 = c2; i0 = d0; i1 = d1; i2 = d2;
        }

        if (seg == 0) {
            float qn = qx * qx + qy * qy + qz * qz;
            float e0 = fmaxf(sqrtf(fmaxf(qn + 2.f * r0, 0.f)), MIN_DIST);
            float e1 = fmaxf(sqrtf(fmaxf(qn + 2.f * r1, 0.f)), MIN_DIST);
            float e2 = fmaxf(sqrtf(fmaxf(qn + 2.f * r2, 0.f)), MIN_DIST);
            float w0 = 1.f / e0, w1 = 1.f / e1, w2 = 1.f / e2;
            float inv = 1.f / (w0 + w1 + w2);
            size_t on = ((size_t)b * N1 + n) * 3;
            g_knn_idx[on] = i0; g_knn_idx[on + 1] = i1; g_knn_idx[on + 2] = i2;
            g_knn_w[on] = w0 * inv; g_knn_w[on + 1] = w1 * inv; g_knn_w[on + 2] = w2 * inv;
        }
    } else if (bid < PREP_KNN + PREP_TP2) {
        // ---- role 1: transpose points2 [B,C2,N2] -> fp16 [B,N2,C2] ----
        float (*tile)[33] = (float (*)[33])sm_raw;
        int idx = bid - PREP_KNN;                    // dim (n:64, c:4, b:8)
        int b  = idx >> 8;
        int rem = idx & 255;
        int c0 = (rem >> 6) << 6;
        int n0 = (rem & 63) << 5;
        int tx = t & 31, ty = t >> 5;
        #pragma unroll
        for (int i = ty; i < 64; i += 8)
            tile[i][tx] = p2[(size_t)b * C2 * N2 + (size_t)(c0 + i) * N2 + n0 + tx];
        __syncthreads();
        #pragma unroll
        for (int i = 0; i < 4; i++) {
            int n = ty * 4 + i;
            __half h0 = __float2half_rn(tile[tx * 2][n]);
            __half h1 = __float2half_rn(tile[tx * 2 + 1][n]);
            uint32_t pk = (uint32_t)__half_as_ushort(h0) | ((uint32_t)__half_as_ushort(h1) << 16);
            *(uint32_t*)&g_p2Th[((size_t)b * N2 + n0 + n) * C2 + c0 + tx * 2] = pk;
        }
    } else if (bid < PREP_KNN + PREP_TP2 + PREP_TP1) {
        // ---- role 2: transpose+cvt points1 [B,C1,N1] -> x0 [n][0..127] fp16 ----
        float (*tile)[33] = (float (*)[33])sm_raw;
        int idx = bid - PREP_KNN - PREP_TP2;         // dim (n:256, c:2, b:8)
        int b  = idx >> 9;
        int rem = idx & 511;
        int c0 = (rem >> 8) << 6;
        int n0 = (rem & 255) << 5;
        int tx = t & 31, ty = t >> 5;
        #pragma unroll
        for (int i = ty; i < 64; i += 8)
            tile[i][tx] = p1[(size_t)b * C1 * N1 + (size_t)(c0 + i) * N1 + n0 + tx];
        __syncthreads();
        #pragma unroll
        for (int i = 0; i < 4; i++) {
            int n = ty * 4 + i;
            __half h0 = __float2half_rn(tile[tx * 2][n]);
            __half h1 = __float2half_rn(tile[tx * 2 + 1][n]);
            uint32_t pk = (uint32_t)__half_as_ushort(h0) | ((uint32_t)__half_as_ushort(h1) << 16);
            *(uint32_t*)&g_x0[((size_t)b * N1 + n0 + n) * KIN1 + c0 + tx * 2] = pk;
        }
    } else {
        // ---- role 3: weight cvt fp32->fp16 + BN-stats zero (graph replays!) ----
        int i = (bid - PREP_KNN - PREP_TP2 - PREP_TP1) * 256 + t;
        if (i < O1 * KIN1) g_w0[i] = __float2half_rn(w0s[i]);
        if (i < O2 * O1)   g_w1[i] = __float2half_rn(w1s[i]);
        if (i < O1) { g_sum0[i] = 0.f; g_sq0[i] = 0.f; }
        if (i < O2) { g_sum1[i] = 0.f; g_sq1[i] = 0.f; }
    }
}

// ---------------- interpolation (fp16 gather) -> x0 [n][128..383] fp16 ----------------
__global__ __launch_bounds__(256) void interp_kernel() {
    __shared__ int   s_idx[96];
    __shared__ float s_w[96];
    int b  = blockIdx.x >> 8;
    int n0 = (blockIdx.x & 255) << 5;
    int t  = threadIdx.x;
    if (t < 96) {
        size_t base = ((size_t)b * N1 + n0) * 3 + t;
        s_idx[t] = g_knn_idx[base];
        s_w[t]   = g_knn_w[base];
    }
    __syncthreads();
    int c = t;
    #pragma unroll 8
    for (int p = 0; p < 32; p++) {
        int k = p * 3;
        const __half* r0 = g_p2Th + ((size_t)b * N2 + s_idx[k + 0]) * C2 + c;
        const __half* r1 = g_p2Th + ((size_t)b * N2 + s_idx[k + 1]) * C2 + c;
        const __half* r2 = g_p2Th + ((size_t)b * N2 + s_idx[k + 2]) * C2 + c;
        float v = fmaf(s_w[k], __half2float(*r0),
                  fmaf(s_w[k + 1], __half2float(*r1),
                       s_w[k + 2] * __half2float(*r2)));
        g_x0[((size_t)b * N1 + n0 + p) * KIN1 + C1 + c] = __float2half_rn(v);
    }
}

// ---------------- mma.sync conv, single-pass fp16 ----------------
// CTA 128x128, 8 warps (2x4 -> 64x32 each), K-chunk 64, cp.async double buffer.
// SMEM rows padded to 72 fp16 (144 B) -> conflict-free ldmatrix.
// NOTE: mainloop is proven; do not touch. (256,2) spills accumulators (R7).
#define SM_A0 0
#define SM_A1 18432
#define SM_B0 36864
#define SM_B1 55296
#define SMEM_MMA 73728

template <int LAYER>
__global__ void __launch_bounds__(256, 1) conv_mma_kernel(const float* __restrict__ bias) {
    constexpr int K   = (LAYER == 0) ? KIN1 : O1;
    constexpr int NCH = K / 64;
    extern __shared__ char smem[];
    uint32_t sb = smem_u32(smem);

    int tid  = threadIdx.x;
    int lane = tid & 31, wid = tid >> 5;
    int m_off = (wid >> 2) * 64;     // warp m-origin (o)
    int n_off = (wid & 3) * 32;      // warp n-origin (points)
    int b  = blockIdx.x >> 6;
    int n0 = (blockIdx.x & 63) << 7;
    int o0 = blockIdx.y << 7;

    const __half* Wbase = ((LAYER == 0) ? g_w0 : g_w1) + (size_t)o0 * K;
    const __half* Xbase = ((LAYER == 0) ? g_x0 : g_x2) + ((size_t)b * N1 + n0) * K;

    uint32_t lm_off = (uint32_t)(((lane & 7) + ((lane >> 3) & 1) * 8) * 144 + (lane >> 4) * 16);

    float acc[4][4][4];
    #pragma unroll
    for (int mi = 0; mi < 4; mi++)
        #pragma unroll
        for (int ni = 0; ni < 4; ni++)
            #pragma unroll
            for (int r = 0; r < 4; r++) acc[mi][ni][r] = 0.f;

    int ld_row = tid >> 3;           // 32 rows per i-step
    int ld_seg = tid & 7;

    auto issue_chunk = [&](int c, int buf) {
        int kk = c * 64;
        uint32_t A  = sb + (buf ? SM_A1 : SM_A0);
        uint32_t Bf = sb + (buf ? SM_B1 : SM_B0);
        #pragma unroll
        for (int i = 0; i < 4; i++) {
            int row = ld_row + i * 32;
            uint32_t d = (uint32_t)(row * 144 + ld_seg * 16);
            cp16(A + d,  Wbase + (size_t)row * K + kk + ld_seg * 8);
            cp16(Bf + d, Xbase + (size_t)row * K + kk + ld_seg * 8);
        }
        cp_commit();
    };

    issue_chunk(0, 0);
    for (int c = 0; c < NCH; c++) {
        int buf = c & 1;
        if (c + 1 < NCH) { issue_chunk(c + 1, buf ^ 1); cp_wait<1>(); }
        else             { cp_wait<0>(); }
        __syncthreads();

        uint32_t A  = sb + (buf ? SM_A1 : SM_A0) + (uint32_t)(m_off * 144) + lm_off;
        uint32_t Bf = sb + (buf ? SM_B1 : SM_B0) + (uint32_t)(n_off * 144) + lm_off;
        #pragma unroll
        for (int kst = 0; kst < 4; kst++) {
            uint32_t af[4][4], bf[2][4];
            #pragma unroll
            for (int mi = 0; mi < 4; mi++)
                ldmx4(A + (uint32_t)(mi * 16 * 144 + kst * 32),
                      af[mi][0], af[mi][1], af[mi][2], af[mi][3]);
            #pragma unroll
            for (int nj = 0; nj < 2; nj++)
                ldmx4(Bf + (uint32_t)(nj * 16 * 144 + kst * 32),
                      bf[nj][0], bf[nj][1], bf[nj][2], bf[nj][3]);
            #pragma unroll
            for (int mi = 0; mi < 4; mi++)
                #pragma unroll
                for (int ni = 0; ni < 4; ni++)
                    mma16816(acc[mi][ni], af[mi],
                             bf[ni >> 1][ni & 1], bf[ni >> 1][(ni & 1) + 2]);
        }
        __syncthreads();
    }

    // ---- epilogue: stage D to SMEM [o][n] stride 129, then stats + stores ----
    float* sD = (float*)smem;
    #pragma unroll
    for (int mi = 0; mi < 4; mi++) {
        int r0 = m_off + mi * 16 + (lane >> 2);
        #pragma unroll
        for (int ni = 0; ni < 4; ni++) {
            int cc = n_off + ni * 8 + (lane & 3) * 2;
            sD[r0 * 129 + cc]           = acc[mi][ni][0];
            sD[r0 * 129 + cc + 1]       = acc[mi][ni][1];
            sD[(r0 + 8) * 129 + cc]     = acc[mi][ni][2];
            sD[(r0 + 8) * 129 + cc + 1] = acc[mi][ni][3];
        }
    }
    __syncthreads();

    {
        int o = tid & 127;
        int nlo = (tid >> 7) * 64;
        float bi = bias[o0 + o];
        float s = 0.f, s2 = 0.f;
        #pragma unroll 4
        for (int n = nlo; n < nlo + 64; n++) {
            float v = sD[o * 129 + n] + bi;
            s += v;
            s2 = fmaf(v, v, s2);
        }
        float* gs = (LAYER == 0) ? g_sum0 : g_sum1;
        float* gq = (LAYER == 0) ? g_sq0  : g_sq1;
        atomicAdd(&gs[o0 + o], s);
        atomicAdd(&gq[o0 + o], s2);
    }

    if (LAYER == 0) {
        for (int e = tid; e < 128 * 128; e += 256) {
            int n = e >> 7, o = e & 127;
            g_y1T[((size_t)b * N1 + n0 + n) * O1 + o0 + o] = sD[o * 129 + n] + bias[o0 + o];
        }
    } else {
        for (int e = tid; e < 128 * 128; e += 256) {
            int o = e >> 7, n = e & 127;
            g_y2[((size_t)b * O2 + o) * N1 + n0 + n] = sD[o * 129 + n] + bias[o];
        }
    }
}

// ---------------- midpass: y1T (fp32) -> BN0(in-block finalize)+ReLU -> x2 fp16 ----------------
__global__ __launch_bounds__(256) void midpass_kernel(const float* __restrict__ gamma0,
                                                      const float* __restrict__ beta0) {
    __shared__ float s_sc[O1], s_sh[O1];
    int t = threadIdx.x;
    {   // per-block BN0 finalize (conv0 kernel boundary ordered the atomics)
        const float inv = 1.0f / (float)P_TOTAL;
        float mu  = g_sum0[t] * inv;
        float var = g_sq0[t] * inv - mu * mu;
        float sc  = gamma0[t] * rsqrtf(var + BN_EPS);
        s_sc[t] = sc;
        s_sh[t] = beta0[t] - mu * sc;
    }
    __syncthreads();

    size_t i4 = (size_t)blockIdx.x * 256 + t;   // float4 index
    float4 v = ((const float4*)g_y1T)[i4];
    int c0 = (int)((i4 * 4) & (O1 - 1));
    float r[4] = {v.x, v.y, v.z, v.w};
    unsigned short h[4];
    #pragma unroll
    for (int j = 0; j < 4; j++) {
        float x = fmaxf(fmaf(r[j], s_sc[c0 + j], s_sh[c0 + j]), 0.f);
        h[j] = __half_as_ushort(__float2half_rn(x));
    }
    ((uint2*)g_x2)[i4] = make_uint2((uint32_t)h[0] | ((uint32_t)h[1] << 16),
                                    (uint32_t)h[2] | ((uint32_t)h[3] << 16));
}

// ---------------- final: BN1(in-block finalize)+ReLU -> output ----------------
// Each block spans 1024 consecutive floats inside one channel row -> one (sc, sh).
__global__ __launch_bounds__(256) void final_kernel(const float* __restrict__ gamma1,
                                                    const float* __restrict__ beta1,
                                                    float* __restrict__ out) {
    __shared__ float s_sc, s_sh;
    int i = blockIdx.x * 256 + threadIdx.x;
    int c = ((i * 4) / N1) & (O2 - 1);
    if (threadIdx.x == 0) {
        const float inv = 1.0f / (float)P_TOTAL;
        float mu  = g_sum1[c] * inv;
        float var = g_sq1[c] * inv - mu * mu;
        float sc  = gamma1[c] * rsqrtf(var + BN_EPS);
        s_sc = sc;
        s_sh = beta1[c] - mu * sc;
    }
    __syncthreads();
    float4 v = ((const float4*)g_y2)[i];
    float sc = s_sc, sh = s_sh;
    v.x = fmaxf(fmaf(v.x, sc, sh), 0.f);
    v.y = fmaxf(fmaf(v.y, sc, sh), 0.f);
    v.z = fmaxf(fmaf(v.z, sc, sh), 0.f);
    v.w = fmaxf(fmaf(v.w, sc, sh), 0.f);
    ((float4*)out)[i] = v;
}

// ---------------- launch ----------------
extern "C" void kernel_launch(void* const* d_in, const int* in_sizes, int n_in,
                              void* d_out, int out_size) {
    const float* xyz1    = (const float*)d_in[0];
    const float* xyz2    = (const float*)d_in[1];
    const float* points1 = (const float*)d_in[2];
    const float* points2 = (const float*)d_in[3];
    const float* w0  = (const float*)d_in[4];
    const float* b0  = (const float*)d_in[5];
    const float* ga0 = (const float*)d_in[6];
    const float* be0 = (const float*)d_in[7];
    const float* w1  = (const float*)d_in[8];
    const float* b1  = (const float*)d_in[9];
    const float* ga1 = (const float*)d_in[10];
    const float* be1 = (const float*)d_in[11];
    float* out = (float*)d_out;

    cudaFuncSetAttribute(conv_mma_kernel<0>, cudaFuncAttributeMaxDynamicSharedMemorySize, SMEM_MMA);
    cudaFuncSetAttribute(conv_mma_kernel<1>, cudaFuncAttributeMaxDynamicSharedMemorySize, SMEM_MMA);

    prep_kernel<<<PREP_TOTAL, 256, PREP_SMEM>>>(xyz1, xyz2, points2, points1, w0, w1);
    interp_kernel<<<BB * (N1 / 32), 256>>>();
    conv_mma_kernel<0><<<dim3(BB * (N1 / 128), O1 / 128), 256, SMEM_MMA>>>(b0);
    midpass_kernel<<<(BB * N1 * O1 / 4) / 256, 256>>>(ga0, be0);
    conv_mma_kernel<1><<<dim3(BB * (N1 / 128), O2 / 128), 256, SMEM_MMA>>>(b1);
    final_kernel<<<(BB * O2 * N1 / 4) / 256, 256>>>(ga1, be1, out);
}

// round 15
// speedup vs baseline: 1.2214x; 1.0636x over previous
#include <cuda_runtime.h>
#include <cuda_fp16.h>
#include <math.h>
#include <stdint.h>

#define BB 8
#define N1 8192
#define N2 2048
#define C1 128
#define C2 256
#define KIN1 384
#define O1 256
#define O2 128
#define BN_EPS 1e-5f
#define MIN_DIST 1e-10f
#define P_TOTAL (BB * N1)

// ---------------- scratch (no allocations allowed) ----------------
__device__ __half g_p2Th[BB * N2 * C2];               // points2 transposed [B][N2][C2], fp16
__device__ int   g_knn_idx[BB * N1 * 3];
__device__ float g_knn_w[BB * N1 * 3];
__device__ __half g_w0[O1 * KIN1];
__device__ __half g_w1[O2 * O1];
__device__ __half g_x0[BB * N1 * KIN1];               // conv0 B operand [n][k] fp16
__device__ __half g_x2[BB * N1 * O1];                 // conv1 B operand [n][k] fp16
__device__ float g_y1T[BB * N1 * O1];                 // conv0 out (pre-BN) fp32, [n][o]
__device__ float g_y2[BB * O2 * N1];                  // conv1 out (pre-BN), channel-major [o][n]
__device__ float g_sum0[O1], g_sq0[O1], g_sum1[O2], g_sq1[O2];

// ---------------- helpers ----------------
__device__ __forceinline__ uint32_t smem_u32(const void* p) {
    return (uint32_t)__cvta_generic_to_shared(p);
}
__device__ __forceinline__ void cp16(uint32_t dst, const void* src) {
    asm volatile("cp.async.ca.shared.global [%0], [%1], 16;" :: "r"(dst), "l"(src));
}
__device__ __forceinline__ void cp_commit() {
    asm volatile("cp.async.commit_group;" ::: "memory");
}
template <int N>
__device__ __forceinline__ void cp_wait() {
    asm volatile("cp.async.wait_group %0;" :: "n"(N) : "memory");
}
__device__ __forceinline__ void ldmx4(uint32_t a, uint32_t& r0, uint32_t& r1,
                                      uint32_t& r2, uint32_t& r3) {
    asm volatile("ldmatrix.sync.aligned.m8n8.x4.shared.b16 {%0,%1,%2,%3}, [%4];"
                 : "=r"(r0), "=r"(r1), "=r"(r2), "=r"(r3) : "r"(a));
}
__device__ __forceinline__ void mma16816(float* c, const uint32_t* a,
                                         uint32_t b0, uint32_t b1) {
    asm volatile("mma.sync.aligned.m16n8k16.row.col.f32.f16.f16.f32 "
                 "{%0,%1,%2,%3},{%4,%5,%6,%7},{%8,%9},{%0,%1,%2,%3};"
                 : "+f"(c[0]), "+f"(c[1]), "+f"(c[2]), "+f"(c[3])
                 : "r"(a[0]), "r"(a[1]), "r"(a[2]), "r"(a[3]), "r"(b0), "r"(b1));
}
__device__ __forceinline__ bool knn_lt(float ra, int ia, float rb, int ib) {
    return (ra < rb) || (ra == rb && ia < ib);
}

// ================= fused prep kernel: grid-partitioned roles =================
// blocks [0, 1024)      : knn (R11-proven 4-lane split, 64 queries/block)
// blocks [1024, 3072)   : transpose_p2 -> fp16 [B,N2,C2]
// blocks [3072, 7168)   : transpose_p1 -> x0[:, 0..127] fp16
// blocks [7168, 7552)   : weight cvt + BN-stats zero
#define PREP_KNN    1024
#define PREP_TP2    2048
#define PREP_TP1    4096
#define PREP_CVT    384
#define PREP_TOTAL  (PREP_KNN + PREP_TP2 + PREP_TP1 + PREP_CVT)
#define PREP_SMEM   33792

__global__ __launch_bounds__(256) void prep_kernel(const float* __restrict__ xyz1,
                                                   const float* __restrict__ xyz2,
                                                   const float* __restrict__ p2,
                                                   const float* __restrict__ p1,
                                                   const float* __restrict__ w0s,
                                                   const float* __restrict__ w1s) {
    extern __shared__ char sm_raw[];
    int bid = blockIdx.x;
    int t   = threadIdx.x;

    if (bid < PREP_KNN) {
        // ---- role 0: 3-NN, 4 segment-lanes/query, shfl merge ----
        float4* s_p = (float4*)sm_raw;   // (x, y, z, 0.5*|p|^2)
        int b  = bid >> 7;
        int n0 = (bid & 127) << 6;
        const float* x2 = xyz2 + (size_t)b * N2 * 3;
        for (int j = t; j < N2; j += 256) {
            float px = x2[j * 3], py = x2[j * 3 + 1], pz = x2[j * 3 + 2];
            s_p[j] = make_float4(px, py, pz, 0.5f * (px * px + py * py + pz * pz));
        }
        __syncthreads();

        int w = t >> 5, lane = t & 31;
        int seg = lane >> 3;
        int n = n0 + w * 8 + (lane & 7);
        const float* q = xyz1 + ((size_t)b * N1 + n) * 3;
        float qx = q[0], qy = q[1], qz = q[2];

        float r0 = 3.4e38f, r1 = 3.4e38f, r2 = 3.4e38f;
        int   i0 = 0, i1 = 0, i2 = 0;
        #pragma unroll 4
        for (int jj = 0; jj < N2 / 4; jj++) {
            int j = (jj << 2) | seg;
            float4 p = s_p[j];
            float r = fmaf(-qx, p.x, fmaf(-qy, p.y, fmaf(-qz, p.z, p.w)));
            if (r < r2) {
                if (r < r1) {
                    r2 = r1; i2 = i1;
                    if (r < r0) { r1 = r0; i1 = i0; r0 = r; i0 = j; }
                    else        { r1 = r; i1 = j; }
                } else { r2 = r; i2 = j; }
            }
        }

        #pragma unroll
        for (int m = 8; m <= 16; m <<= 1) {
            float s0 = __shfl_xor_sync(0xffffffff, r0, m);
            float s1 = __shfl_xor_sync(0xffffffff, r1, m);
            float s2 = __shfl_xor_sync(0xffffffff, r2, m);
            int   j0 = __shfl_xor_sync(0xffffffff, i0, m);
            int   j1 = __shfl_xor_sync(0xffffffff, i1, m);
            int   j2 = __shfl_xor_sync(0xffffffff, i2, m);
            float c0, c1, c2; int d0, d1, d2;
            if (knn_lt(r0, i0, s0, j0)) {
                c0 = r0; d0 = i0;
                if (knn_lt(r1, i1, s0, j0)) {
                    c1 = r1; d1 = i1;
                    if (knn_lt(r2, i2, s0, j0)) { c2 = r2; d2 = i2; }
                    else                        { c2 = s0; d2 = j0; }
                } else {
                    c1 = s0; d1 = j0;
                    if (knn_lt(r1, i1, s1, j1)) { c2 = r1; d2 = i1; }
                    else                        { c2 = s1; d2 = j1; }
                }
            } else {
                c0 = s0; d0 = j0;
                if (knn_lt(s1, j1, r0, i0)) {
                    c1 = s1; d1 = j1;
                    if (knn_lt(s2, j2, r0, i0)) { c2 = s2; d2 = j2; }
                    else                        { c2 = r0; d2 = i0; }
                } else {
                    c1 = r0; d1 = i0;
                    if (knn_lt(r1, i1, s1, j1)) { c2 = r1; d2 = i1; }
                    else                        { c2 = s1; d2 = j1; }
                }
            }
            r0 = c0; r1 = c1; r2 = c2; i0 = d0; i1 = d1; i2 = d2;
        }

        if (seg == 0) {
            float qn = qx * qx + qy * qy + qz * qz;
            float e0 = fmaxf(sqrtf(fmaxf(qn + 2.f * r0, 0.f)), MIN_DIST);
            float e1 = fmaxf(sqrtf(fmaxf(qn + 2.f * r1, 0.f)), MIN_DIST);
            float e2 = fmaxf(sqrtf(fmaxf(qn + 2.f * r2, 0.f)), MIN_DIST);
            float w0 = 1.f / e0, w1 = 1.f / e1, w2 = 1.f / e2;
            float inv = 1.f / (w0 + w1 + w2);
            size_t on = ((size_t)b * N1 + n) * 3;
            g_knn_idx[on] = i0; g_knn_idx[on + 1] = i1; g_knn_idx[on + 2] = i2;
            g_knn_w[on] = w0 * inv; g_knn_w[on + 1] = w1 * inv; g_knn_w[on + 2] = w2 * inv;
        }
    } else if (bid < PREP_KNN + PREP_TP2) {
        // ---- role 1: transpose points2 [B,C2,N2] -> fp16 [B,N2,C2] ----
        float (*tile)[33] = (float (*)[33])sm_raw;
        int idx = bid - PREP_KNN;
        int b  = idx >> 8;
        int rem = idx & 255;
        int c0 = (rem >> 6) << 6;
        int n0 = (rem & 63) << 5;
        int tx = t & 31, ty = t >> 5;
        #pragma unroll
        for (int i = ty; i < 64; i += 8)
            tile[i][tx] = p2[(size_t)b * C2 * N2 + (size_t)(c0 + i) * N2 + n0 + tx];
        __syncthreads();
        #pragma unroll
        for (int i = 0; i < 4; i++) {
            int n = ty * 4 + i;
            __half h0 = __float2half_rn(tile[tx * 2][n]);
            __half h1 = __float2half_rn(tile[tx * 2 + 1][n]);
            uint32_t pk = (uint32_t)__half_as_ushort(h0) | ((uint32_t)__half_as_ushort(h1) << 16);
            *(uint32_t*)&g_p2Th[((size_t)b * N2 + n0 + n) * C2 + c0 + tx * 2] = pk;
        }
    } else if (bid < PREP_KNN + PREP_TP2 + PREP_TP1) {
        // ---- role 2: transpose+cvt points1 [B,C1,N1] -> x0 [n][0..127] fp16 ----
        float (*tile)[33] = (float (*)[33])sm_raw;
        int idx = bid - PREP_KNN - PREP_TP2;
        int b  = idx >> 9;
        int rem = idx & 511;
        int c0 = (rem >> 8) << 6;
        int n0 = (rem & 255) << 5;
        int tx = t & 31, ty = t >> 5;
        #pragma unroll
        for (int i = ty; i < 64; i += 8)
            tile[i][tx] = p1[(size_t)b * C1 * N1 + (size_t)(c0 + i) * N1 + n0 + tx];
        __syncthreads();
        #pragma unroll
        for (int i = 0; i < 4; i++) {
            int n = ty * 4 + i;
            __half h0 = __float2half_rn(tile[tx * 2][n]);
            __half h1 = __float2half_rn(tile[tx * 2 + 1][n]);
            uint32_t pk = (uint32_t)__half_as_ushort(h0) | ((uint32_t)__half_as_ushort(h1) << 16);
            *(uint32_t*)&g_x0[((size_t)b * N1 + n0 + n) * KIN1 + c0 + tx * 2] = pk;
        }
    } else {
        // ---- role 3: weight cvt fp32->fp16 + BN-stats zero (graph replays!) ----
        int i = (bid - PREP_KNN - PREP_TP2 - PREP_TP1) * 256 + t;
        if (i < O1 * KIN1) g_w0[i] = __float2half_rn(w0s[i]);
        if (i < O2 * O1)   g_w1[i] = __float2half_rn(w1s[i]);
        if (i < O1) { g_sum0[i] = 0.f; g_sq0[i] = 0.f; }
        if (i < O2) { g_sum1[i] = 0.f; g_sq1[i] = 0.f; }
    }
}

// ---------------- interpolation (half2 gather, full-sector warps) ----------------
// thread t: channel pair cp = t&127 (channels 2cp, 2cp+1), point parity t>>7.
// Warp reads 128B contiguous per gathered row; x0 written as packed u32.
__global__ __launch_bounds__(256) void interp_kernel() {
    __shared__ int   s_idx[96];
    __shared__ float s_w[96];
    int b  = blockIdx.x >> 8;
    int n0 = (blockIdx.x & 255) << 5;
    int t  = threadIdx.x;
    if (t < 96) {
        size_t base = ((size_t)b * N1 + n0) * 3 + t;
        s_idx[t] = g_knn_idx[base];
        s_w[t]   = g_knn_w[base];
    }
    __syncthreads();
    int cp   = t & 127;          // channel pair 0..127
    int par  = t >> 7;           // point parity 0/1
    #pragma unroll 4
    for (int pp = 0; pp < 16; pp++) {
        int p = pp * 2 + par;
        int k = p * 3;
        uint32_t v0 = *(const uint32_t*)&g_p2Th[((size_t)b * N2 + s_idx[k + 0]) * C2 + 2 * cp];
        uint32_t v1 = *(const uint32_t*)&g_p2Th[((size_t)b * N2 + s_idx[k + 1]) * C2 + 2 * cp];
        uint32_t v2 = *(const uint32_t*)&g_p2Th[((size_t)b * N2 + s_idx[k + 2]) * C2 + 2 * cp];
        float w0 = s_w[k], w1 = s_w[k + 1], w2 = s_w[k + 2];
        float2 a0 = __half22float2(*(__half2*)&v0);
        float2 a1 = __half22float2(*(__half2*)&v1);
        float2 a2 = __half22float2(*(__half2*)&v2);
        float lo = fmaf(w0, a0.x, fmaf(w1, a1.x, w2 * a2.x));
        float hi = fmaf(w0, a0.y, fmaf(w1, a1.y, w2 * a2.y));
        uint32_t pk = (uint32_t)__half_as_ushort(__float2half_rn(lo))
                    | ((uint32_t)__half_as_ushort(__float2half_rn(hi)) << 16);
        *(uint32_t*)&g_x0[((size_t)b * N1 + n0 + p) * KIN1 + C1 + 2 * cp] = pk;
    }
}

// ---------------- mma.sync conv, single-pass fp16 ----------------
// CTA 128x128, 8 warps (2x4 -> 64x32 each), K-chunk 64, cp.async double buffer.
// SMEM rows padded to 72 fp16 (144 B) -> conflict-free ldmatrix.
// NOTE: mainloop is proven; do not touch. (256,2) spills accumulators (R7).
#define SM_A0 0
#define SM_A1 18432
#define SM_B0 36864
#define SM_B1 55296
#define SMEM_MMA 73728

template <int LAYER>
__global__ void __launch_bounds__(256, 1) conv_mma_kernel(const float* __restrict__ bias) {
    constexpr int K   = (LAYER == 0) ? KIN1 : O1;
    constexpr int NCH = K / 64;
    extern __shared__ char smem[];
    uint32_t sb = smem_u32(smem);

    int tid  = threadIdx.x;
    int lane = tid & 31, wid = tid >> 5;
    int m_off = (wid >> 2) * 64;
    int n_off = (wid & 3) * 32;
    int b  = blockIdx.x >> 6;
    int n0 = (blockIdx.x & 63) << 7;
    int o0 = blockIdx.y << 7;

    const __half* Wbase = ((LAYER == 0) ? g_w0 : g_w1) + (size_t)o0 * K;
    const __half* Xbase = ((LAYER == 0) ? g_x0 : g_x2) + ((size_t)b * N1 + n0) * K;

    uint32_t lm_off = (uint32_t)(((lane & 7) + ((lane >> 3) & 1) * 8) * 144 + (lane >> 4) * 16);

    float acc[4][4][4];
    #pragma unroll
    for (int mi = 0; mi < 4; mi++)
        #pragma unroll
        for (int ni = 0; ni < 4; ni++)
            #pragma unroll
            for (int r = 0; r < 4; r++) acc[mi][ni][r] = 0.f;

    int ld_row = tid >> 3;
    int ld_seg = tid & 7;

    auto issue_chunk = [&](int c, int buf) {
        int kk = c * 64;
        uint32_t A  = sb + (buf ? SM_A1 : SM_A0);
        uint32_t Bf = sb + (buf ? SM_B1 : SM_B0);
        #pragma unroll
        for (int i = 0; i < 4; i++) {
            int row = ld_row + i * 32;
            uint32_t d = (uint32_t)(row * 144 + ld_seg * 16);
            cp16(A + d,  Wbase + (size_t)row * K + kk + ld_seg * 8);
            cp16(Bf + d, Xbase + (size_t)row * K + kk + ld_seg * 8);
        }
        cp_commit();
    };

    issue_chunk(0, 0);
    for (int c = 0; c < NCH; c++) {
        int buf = c & 1;
        if (c + 1 < NCH) { issue_chunk(c + 1, buf ^ 1); cp_wait<1>(); }
        else             { cp_wait<0>(); }
        __syncthreads();

        uint32_t A  = sb + (buf ? SM_A1 : SM_A0) + (uint32_t)(m_off * 144) + lm_off;
        uint32_t Bf = sb + (buf ? SM_B1 : SM_B0) + (uint32_t)(n_off * 144) + lm_off;
        #pragma unroll
        for (int kst = 0; kst < 4; kst++) {
            uint32_t af[4][4], bf[2][4];
            #pragma unroll
            for (int mi = 0; mi < 4; mi++)
                ldmx4(A + (uint32_t)(mi * 16 * 144 + kst * 32),
                      af[mi][0], af[mi][1], af[mi][2], af[mi][3]);
            #pragma unroll
            for (int nj = 0; nj < 2; nj++)
                ldmx4(Bf + (uint32_t)(nj * 16 * 144 + kst * 32),
                      bf[nj][0], bf[nj][1], bf[nj][2], bf[nj][3]);
            #pragma unroll
            for (int mi = 0; mi < 4; mi++)
                #pragma unroll
                for (int ni = 0; ni < 4; ni++)
                    mma16816(acc[mi][ni], af[mi],
                             bf[ni >> 1][ni & 1], bf[ni >> 1][(ni & 1) + 2]);
        }
        __syncthreads();
    }

    // ---- epilogue: stage D to SMEM [o][n] stride 129, then stats + stores ----
    float* sD = (float*)smem;
    #pragma unroll
    for (int mi = 0; mi < 4; mi++) {
        int r0 = m_off + mi * 16 + (lane >> 2);
        #pragma unroll
        for (int ni = 0; ni < 4; ni++) {
            int cc = n_off + ni * 8 + (lane & 3) * 2;
            sD[r0 * 129 + cc]           = acc[mi][ni][0];
            sD[r0 * 129 + cc + 1]       = acc[mi][ni][1];
            sD[(r0 + 8) * 129 + cc]     = acc[mi][ni][2];
            sD[(r0 + 8) * 129 + cc + 1] = acc[mi][ni][3];
        }
    }
    __syncthreads();

    {
        int o = tid & 127;
        int nlo = (tid >> 7) * 64;
        float bi = bias[o0 + o];
        float s = 0.f, s2 = 0.f;
        #pragma unroll 4
        for (int n = nlo; n < nlo + 64; n++) {
            float v = sD[o * 129 + n] + bi;
            s += v;
            s2 = fmaf(v, v, s2);
        }
        float* gs = (LAYER == 0) ? g_sum0 : g_sum1;
        float* gq = (LAYER == 0) ? g_sq0  : g_sq1;
        atomicAdd(&gs[o0 + o], s);
        atomicAdd(&gq[o0 + o], s2);
    }

    if (LAYER == 0) {
        for (int e = tid; e < 128 * 128; e += 256) {
            int n = e >> 7, o = e & 127;
            g_y1T[((size_t)b * N1 + n0 + n) * O1 + o0 + o] = sD[o * 129 + n] + bias[o0 + o];
        }
    } else {
        for (int e = tid; e < 128 * 128; e += 256) {
            int o = e >> 7, n = e & 127;
            g_y2[((size_t)b * O2 + o) * N1 + n0 + n] = sD[o * 129 + n] + bias[o];
        }
    }
}

// ---------------- midpass: y1T (fp32) -> BN0(in-block finalize)+ReLU -> x2 fp16, MLP=4 ----------------
__global__ __launch_bounds__(256) void midpass_kernel(const float* __restrict__ gamma0,
                                                      const float* __restrict__ beta0) {
    __shared__ float s_sc[O1], s_sh[O1];
    int t = threadIdx.x;
    {
        const float inv = 1.0f / (float)P_TOTAL;
        float mu  = g_sum0[t] * inv;
        float var = g_sq0[t] * inv - mu * mu;
        float sc  = gamma0[t] * rsqrtf(var + BN_EPS);
        s_sc[t] = sc;
        s_sh[t] = beta0[t] - mu * sc;
    }
    __syncthreads();

    size_t base = (size_t)blockIdx.x * 1024 + t;   // 4 float4 per thread, stride 256
    float4 v[4];
    #pragma unroll
    for (int kchunk = 0; kchunk < 4; kchunk++)
        v[kchunk] = ((const float4*)g_y1T)[base + kchunk * 256];
    int c0 = (int)((4 * t) & (O1 - 1));            // invariant across chunks (stride 1024 floats)
    float sc0 = s_sc[c0], sh0 = s_sh[c0];
    float sc1 = s_sc[c0 + 1], sh1 = s_sh[c0 + 1];
    float sc2 = s_sc[c0 + 2], sh2 = s_sh[c0 + 2];
    float sc3 = s_sc[c0 + 3], sh3 = s_sh[c0 + 3];
    #pragma unroll
    for (int kchunk = 0; kchunk < 4; kchunk++) {
        float x0 = fmaxf(fmaf(v[kchunk].x, sc0, sh0), 0.f);
        float x1 = fmaxf(fmaf(v[kchunk].y, sc1, sh1), 0.f);
        float x2v = fmaxf(fmaf(v[kchunk].z, sc2, sh2), 0.f);
        float x3 = fmaxf(fmaf(v[kchunk].w, sc3, sh3), 0.f);
        uint2 pk = make_uint2(
            (uint32_t)__half_as_ushort(__float2half_rn(x0))
          | ((uint32_t)__half_as_ushort(__float2half_rn(x1)) << 16),
            (uint32_t)__half_as_ushort(__float2half_rn(x2v))
          | ((uint32_t)__half_as_ushort(__float2half_rn(x3)) << 16));
        ((uint2*)g_x2)[base + kchunk * 256] = pk;
    }
}

// ---------------- final: BN1(in-block finalize)+ReLU -> output, MLP=4 ----------------
// Block spans 4096 consecutive floats inside one channel row -> one (sc, sh).
__global__ __launch_bounds__(256) void final_kernel(const float* __restrict__ gamma1,
                                                    const float* __restrict__ beta1,
                                                    float* __restrict__ out) {
    __shared__ float s_scb, s_shb;
    size_t base = (size_t)blockIdx.x * 1024 + threadIdx.x;
    int c = (int)((base * 4) / N1) & (O2 - 1);
    if (threadIdx.x == 0) {
        const float inv = 1.0f / (float)P_TOTAL;
        float mu  = g_sum1[c] * inv;
        float var = g_sq1[c] * inv - mu * mu;
        float sc  = gamma1[c] * rsqrtf(var + BN_EPS);
        s_scb = sc;
        s_shb = beta1[c] - mu * sc;
    }
    __syncthreads();
    float4 v[4];
    #pragma unroll
    for (int kchunk = 0; kchunk < 4; kchunk++)
        v[kchunk] = ((const float4*)g_y2)[base + kchunk * 256];
    float sc = s_scb, sh = s_shb;
    #pragma unroll
    for (int kchunk = 0; kchunk < 4; kchunk++) {
        float4 o;
        o.x = fmaxf(fmaf(v[kchunk].x, sc, sh), 0.f);
        o.y = fmaxf(fmaf(v[kchunk].y, sc, sh), 0.f);
        o.z = fmaxf(fmaf(v[kchunk].z, sc, sh), 0.f);
        o.w = fmaxf(fmaf(v[kchunk].w, sc, sh), 0.f);
        ((float4*)out)[base + kchunk * 256] = o;
    }
}

// ---------------- launch ----------------
extern "C" void kernel_launch(void* const* d_in, const int* in_sizes, int n_in,
                              void* d_out, int out_size) {
    const float* xyz1    = (const float*)d_in[0];
    const float* xyz2    = (const float*)d_in[1];
    const float* points1 = (const float*)d_in[2];
    const float* points2 = (const float*)d_in[3];
    const float* w0  = (const float*)d_in[4];
    const float* b0  = (const float*)d_in[5];
    const float* ga0 = (const float*)d_in[6];
    const float* be0 = (const float*)d_in[7];
    const float* w1  = (const float*)d_in[8];
    const float* b1  = (const float*)d_in[9];
    const float* ga1 = (const float*)d_in[10];
    const float* be1 = (const float*)d_in[11];
    float* out = (float*)d_out;

    cudaFuncSetAttribute(conv_mma_kernel<0>, cudaFuncAttributeMaxDynamicSharedMemorySize, SMEM_MMA);
    cudaFuncSetAttribute(conv_mma_kernel<1>, cudaFuncAttributeMaxDynamicSharedMemorySize, SMEM_MMA);

    prep_kernel<<<PREP_TOTAL, 256, PREP_SMEM>>>(xyz1, xyz2, points2, points1, w0, w1);
    interp_kernel<<<BB * (N1 / 32), 256>>>();
    conv_mma_kernel<0><<<dim3(BB * (N1 / 128), O1 / 128), 256, SMEM_MMA>>>(b0);
    midpass_kernel<<<(BB * N1 * O1 / 4) / 1024, 256>>>(ga0, be0);
    conv_mma_kernel<1><<<dim3(BB * (N1 / 128), O2 / 128), 256, SMEM_MMA>>>(b1);
    final_kernel<<<(BB * O2 * N1 / 4) / 1024, 256>>>(ga1, be1, out);
}